// round 14
// baseline (speedup 1.0000x reference)
#include <cuda_runtime.h>
#include <cuda_fp16.h>

#define CCH 256
#define HH 64
#define WW 64
#define NPIX (HH * WW)

// fp16 channels-last scratch, channel-interleaved within 64-ch groups:
// half2 slot (pixel, g, c') holds channels (g*64 + c', g*64 + 32 + c').
__device__ __half2 g_feat_h[4 * NPIX * (CCH / 2)];

// NCHW fp32 -> interleaved NHWC fp16.
__global__ __launch_bounds__(256) void transpose_kernel(const float* __restrict__ feat)
{
    __shared__ float t_lo[32][33];
    __shared__ float t_hi[32][33];
    const int b  = blockIdx.z;
    const int g  = blockIdx.y;
    const int p0 = blockIdx.x * 32;
    const int tx = threadIdx.x;
    const int ty = threadIdx.y;
    const float* src = feat + (size_t)b * CCH * NPIX;
#pragma unroll
    for (int i = 0; i < 32; i += 8) {
        t_lo[ty + i][tx] = src[(size_t)(g * 64 +      ty + i) * NPIX + (p0 + tx)];
        t_hi[ty + i][tx] = src[(size_t)(g * 64 + 32 + ty + i) * NPIX + (p0 + tx)];
    }
    __syncthreads();
    __half2* dst = g_feat_h + (size_t)b * (NPIX * (CCH / 2));
#pragma unroll
    for (int i = 0; i < 32; i += 8) {
        const int p = p0 + ty + i;
        dst[(size_t)p * (CCH / 2) + g * 32 + tx] =
            __floats2half2_rn(t_lo[tx][ty + i], t_hi[tx][ty + i]);
    }
}

// Dynamic smem layout (bytes):
//   [0,1024)      int4   s_off[64]
//   [1024,2048)   float4 s_w[64]
//   [2048,2064)   int    s_b
//   [2064,52240)  float  s_pool[4][64*49]
#define OFF_POOL 2064
#define SMEM_BYTES (OFF_POOL + 4 * 64 * 49 * 4)

// Block = 256 threads = 8 warps = ONE ROI.
// Warp w: channel group g = w>>1 (64 ch), row-half rh = w&1.
//   rh=0: bin rows 0..4 -> output rows 0..3 (28 positions)
//   rh=1: bin rows 4..7 -> output rows 4..6 (21 positions)
__global__ __launch_bounds__(256, 4) void roialign_maxpool_kernel(
    const float* __restrict__ rois,
    float* __restrict__ out)
{
    extern __shared__ __align__(16) char dyn[];
    int4*   s_off  = (int4*)(dyn);
    float4* s_w    = (float4*)(dyn + 1024);
    int*    s_bp   = (int*)(dyn + 2048);
    float*  s_pool = (float*)(dyn + OFF_POOL);

    const int roi = blockIdx.x;
    const int tid = threadIdx.x;

    // ---- per-ROI geometry, one bin per thread 0..63 (valid folded into w) ----
    if (tid < 64) {
        const float* r = rois + (size_t)roi * 5;
        const float x1 = r[1] * 0.0625f;
        const float y1 = r[2] * 0.0625f;
        const float x2 = r[3] * 0.0625f;
        const float y2 = r[4] * 0.0625f;
        const float bh = (y2 - y1) / 7.0f;
        const float bw = (x2 - x1) / 7.0f;
        const int j = tid >> 3;
        const int i = tid & 7;
        const float ys = y1 + bh * (float)j;
        const float xs = x1 + bw * (float)i;
        const bool valid = (ys >= 0.0f) && (ys < (float)HH) &&
                           (xs >= 0.0f) && (xs < (float)WW);
        const float y0 = floorf(ys);
        const float x0 = floorf(xs);
        const float ly = ys - y0;
        const float lx = xs - x0;
        int iy0 = min(max((int)y0, 0), HH - 1);
        int ix0 = min(max((int)x0, 0), WW - 1);
        int iy1 = min(iy0 + 1, HH - 1);
        int ix1 = min(ix0 + 1, WW - 1);
        float hy = 1.0f - ly, hx = 1.0f - lx;
        float w00 = hy * hx, w01 = hy * lx, w10 = ly * hx, w11 = ly * lx;
        if (!valid) { w00 = 0.0f; w01 = 0.0f; w10 = 0.0f; w11 = 0.0f; }
        // offsets in half2 units: pixel * 128
        s_off[tid] = make_int4((iy0 * WW + ix0) * (CCH / 2), (iy0 * WW + ix1) * (CCH / 2),
                               (iy1 * WW + ix0) * (CCH / 2), (iy1 * WW + ix1) * (CCH / 2));
        s_w[tid] = make_float4(w00, w01, w10, w11);
        if (tid == 0) *s_bp = (int)rois[(size_t)roi * 5];
    }
    __syncthreads();

    const int warp = tid >> 5;
    const int lane = tid & 31;
    const int g    = warp >> 1;
    const int rh   = warp & 1;
    const __half2* p = g_feat_h + (size_t)(*s_bp) * (NPIX * (CCH / 2)) + g * 32 + lane;
    float* pool = s_pool + g * (64 * 49);

    const int jbeg = rh ? 4 : 0;
    const int jend = rh ? 8 : 5;

    float2 prev[8], cur[8];
    for (int j = jbeg; j < jend; j++) {
#pragma unroll
        for (int i = 0; i < 8; i++) {
            const int bin = j * 8 + i;
            const int4   o = s_off[bin];   // LDS.128 broadcast
            const float4 w = s_w[bin];     // LDS.128 broadcast
            const float2 f00 = __half22float2(__ldg(p + o.x));
            const float2 f01 = __half22float2(__ldg(p + o.y));
            const float2 f10 = __half22float2(__ldg(p + o.z));
            const float2 f11 = __half22float2(__ldg(p + o.w));
            cur[i].x = w.x * f00.x + w.y * f01.x + w.z * f10.x + w.w * f11.x;
            cur[i].y = w.x * f00.y + w.y * f01.y + w.z * f10.y + w.w * f11.y;
        }
        if (j > jbeg) {
#pragma unroll
            for (int pw = 0; pw < 7; pw++) {
                const float mx = fmaxf(fmaxf(prev[pw].x, prev[pw + 1].x),
                                       fmaxf(cur[pw].x,  cur[pw + 1].x));
                const float my = fmaxf(fmaxf(prev[pw].y, prev[pw + 1].y),
                                       fmaxf(cur[pw].y,  cur[pw + 1].y));
                const int pos = (j - 1) * 7 + pw;
                // bank (17*lane + pos) mod 32: bijective in lane -> conflict-free
                pool[lane * 49 + pos]        = mx;
                pool[(lane + 32) * 49 + pos] = my;
            }
        }
#pragma unroll
        for (int i = 0; i < 8; i++) prev[i] = cur[i];
    }
    __syncthreads();

    // ---- coalesced float4 flush: group g's pool = 784 float4; each of the
    //      two warps (rh 0/1) flushes 392 of them ----
    float4* obase = (float4*)(out + ((size_t)roi * CCH + g * 64) * 49) + rh * 392;
    const float4* pp = (const float4*)pool + rh * 392;
#pragma unroll
    for (int it = 0; it < 12; it++)
        obase[it * 32 + lane] = pp[it * 32 + lane];
    if (lane < 8)
        obase[384 + lane] = pp[384 + lane];
}

extern "C" void kernel_launch(void* const* d_in, const int* in_sizes, int n_in,
                              void* d_out, int out_size)
{
    const float* feat = (const float*)d_in[0];  // [4,256,64,64] f32
    const float* rois = (const float*)d_in[1];  // [N,5] f32
    float* out = (float*)d_out;                 // [N,256,7,7] f32
    const int N = in_sizes[1] / 5;

    static int smem_set = 0;
    if (!smem_set) {
        cudaFuncSetAttribute(roialign_maxpool_kernel,
                             cudaFuncAttributeMaxDynamicSharedMemorySize, SMEM_BYTES);
        smem_set = 1;
    }

    dim3 tb(32, 8);
    dim3 tg(NPIX / 32, CCH / 64, 4);
    transpose_kernel<<<tg, tb>>>(feat);

    roialign_maxpool_kernel<<<N, 256, SMEM_BYTES>>>(rois, out);
}

// round 15
// speedup vs baseline: 1.1991x; 1.1991x over previous
#include <cuda_runtime.h>
#include <cuda_fp16.h>

#define CCH 256
#define HH 64
#define WW 64
#define NPIX (HH * WW)

// fp16 channels-last scratch, channel-interleaved within 64-ch groups:
// half2 slot (pixel, g, c') holds channels (g*64 + c', g*64 + 32 + c').
__device__ __half2 g_feat_h[4 * NPIX * (CCH / 2)];

// NCHW fp32 -> interleaved NHWC fp16.
__global__ __launch_bounds__(256) void transpose_kernel(const float* __restrict__ feat)
{
    __shared__ float t_lo[32][33];
    __shared__ float t_hi[32][33];
    const int b  = blockIdx.z;
    const int g  = blockIdx.y;
    const int p0 = blockIdx.x * 32;
    const int tx = threadIdx.x;
    const int ty = threadIdx.y;
    const float* src = feat + (size_t)b * CCH * NPIX;
#pragma unroll
    for (int i = 0; i < 32; i += 8) {
        t_lo[ty + i][tx] = src[(size_t)(g * 64 +      ty + i) * NPIX + (p0 + tx)];
        t_hi[ty + i][tx] = src[(size_t)(g * 64 + 32 + ty + i) * NPIX + (p0 + tx)];
    }
    __syncthreads();
    __half2* dst = g_feat_h + (size_t)b * (NPIX * (CCH / 2));
#pragma unroll
    for (int i = 0; i < 32; i += 8) {
        const int p = p0 + ty + i;
        dst[(size_t)p * (CCH / 2) + g * 32 + tx] =
            __floats2half2_rn(t_lo[tx][ty + i], t_hi[tx][ty + i]);
    }
}

// Block = 64 threads (2 warps). Each block: one ROI, 128 channels.
// Warp = one 64-channel group; lane = half2 = channels (c', c'+32).
// Gather pipeline: taps for bin-row j+1 prefetched into a ping-pong
// register buffer while row j is converted/pooled -> ~32 loads always
// in flight per warp (L2-latency hiding).
__global__ __launch_bounds__(64) void roialign_maxpool_kernel(
    const float* __restrict__ rois,
    float* __restrict__ out)
{
    __shared__ int4   s_off[64];
    __shared__ float4 s_w[64];
    __shared__ int    s_b;
    __shared__ __align__(16) float s_pool[2][64 * 49];  // [warp][64ch][49] == output order

    const int roi  = blockIdx.x >> 1;
    const int half = blockIdx.x & 1;
    const int tid  = threadIdx.x;

    // ---- per-ROI geometry, one bin per thread (valid folded into weights) ----
    {
        const float* r = rois + (size_t)roi * 5;
        const float x1 = r[1] * 0.0625f;
        const float y1 = r[2] * 0.0625f;
        const float x2 = r[3] * 0.0625f;
        const float y2 = r[4] * 0.0625f;
        const float bh = (y2 - y1) / 7.0f;
        const float bw = (x2 - x1) / 7.0f;
        const int j = tid >> 3;
        const int i = tid & 7;
        const float ys = y1 + bh * (float)j;
        const float xs = x1 + bw * (float)i;
        const bool valid = (ys >= 0.0f) && (ys < (float)HH) &&
                           (xs >= 0.0f) && (xs < (float)WW);
        const float y0 = floorf(ys);
        const float x0 = floorf(xs);
        const float ly = ys - y0;
        const float lx = xs - x0;
        int iy0 = min(max((int)y0, 0), HH - 1);
        int ix0 = min(max((int)x0, 0), WW - 1);
        int iy1 = min(iy0 + 1, HH - 1);
        int ix1 = min(ix0 + 1, WW - 1);
        float hy = 1.0f - ly, hx = 1.0f - lx;
        float w00 = hy * hx, w01 = hy * lx, w10 = ly * hx, w11 = ly * lx;
        if (!valid) { w00 = 0.0f; w01 = 0.0f; w10 = 0.0f; w11 = 0.0f; }
        // offsets in half2 units: pixel * 128
        s_off[tid] = make_int4((iy0 * WW + ix0) * (CCH / 2), (iy0 * WW + ix1) * (CCH / 2),
                               (iy1 * WW + ix0) * (CCH / 2), (iy1 * WW + ix1) * (CCH / 2));
        s_w[tid] = make_float4(w00, w01, w10, w11);
        if (tid == 0) s_b = (int)rois[(size_t)roi * 5];
    }
    __syncthreads();

    const int warp = tid >> 5;
    const int lane = tid & 31;
    const int g    = half * 2 + warp;     // 64-channel group index
    const __half2* p = g_feat_h + (size_t)s_b * (NPIX * (CCH / 2)) + g * 32 + lane;
    float* pool = &s_pool[warp][0];

    __half2 bufA[8][4], bufB[8][4];

    // prime: issue all 32 loads of row 0
#pragma unroll
    for (int i = 0; i < 8; i++) {
        const int4 o = s_off[i];
        bufA[i][0] = __ldg(p + o.x);
        bufA[i][1] = __ldg(p + o.y);
        bufA[i][2] = __ldg(p + o.z);
        bufA[i][3] = __ldg(p + o.w);
    }

    float2 prev[8], cur[8];
#pragma unroll
    for (int j = 0; j < 8; j++) {
        // prefetch row j+1 into the other buffer
        if (j < 7) {
#pragma unroll
            for (int i = 0; i < 8; i++) {
                const int4 o = s_off[(j + 1) * 8 + i];
                if ((j & 1) == 0) {
                    bufB[i][0] = __ldg(p + o.x);
                    bufB[i][1] = __ldg(p + o.y);
                    bufB[i][2] = __ldg(p + o.z);
                    bufB[i][3] = __ldg(p + o.w);
                } else {
                    bufA[i][0] = __ldg(p + o.x);
                    bufA[i][1] = __ldg(p + o.y);
                    bufA[i][2] = __ldg(p + o.z);
                    bufA[i][3] = __ldg(p + o.w);
                }
            }
        }
        // compute row j from the current buffer
#pragma unroll
        for (int i = 0; i < 8; i++) {
            const float4 w = s_w[j * 8 + i];   // LDS.128 broadcast
            const __half2 h00 = ((j & 1) == 0) ? bufA[i][0] : bufB[i][0];
            const __half2 h01 = ((j & 1) == 0) ? bufA[i][1] : bufB[i][1];
            const __half2 h10 = ((j & 1) == 0) ? bufA[i][2] : bufB[i][2];
            const __half2 h11 = ((j & 1) == 0) ? bufA[i][3] : bufB[i][3];
            const float2 f00 = __half22float2(h00);
            const float2 f01 = __half22float2(h01);
            const float2 f10 = __half22float2(h10);
            const float2 f11 = __half22float2(h11);
            cur[i].x = w.x * f00.x + w.y * f01.x + w.z * f10.x + w.w * f11.x;
            cur[i].y = w.x * f00.y + w.y * f01.y + w.z * f10.y + w.w * f11.y;
        }
        if (j > 0) {
#pragma unroll
            for (int pw = 0; pw < 7; pw++) {
                const float mx = fmaxf(fmaxf(prev[pw].x, prev[pw + 1].x),
                                       fmaxf(cur[pw].x,  cur[pw + 1].x));
                const float my = fmaxf(fmaxf(prev[pw].y, prev[pw + 1].y),
                                       fmaxf(cur[pw].y,  cur[pw + 1].y));
                const int pos = (j - 1) * 7 + pw;
                // bank (17*lane + pos) mod 32: bijective in lane -> conflict-free
                pool[lane * 49 + pos]        = mx;
                pool[(lane + 32) * 49 + pos] = my;
            }
        }
#pragma unroll
        for (int i = 0; i < 8; i++) prev[i] = cur[i];
    }
    __syncwarp();

    // ---- coalesced float4 flush: 64ch * 49 = 784 float4 per warp ----
    float4* obase = (float4*)(out + ((size_t)roi * CCH + g * 64) * 49);
    const float4* pp = (const float4*)pool;
#pragma unroll
    for (int it = 0; it < 24; it++)
        obase[it * 32 + lane] = pp[it * 32 + lane];
    if (lane < 16)
        obase[768 + lane] = pp[768 + lane];
}

extern "C" void kernel_launch(void* const* d_in, const int* in_sizes, int n_in,
                              void* d_out, int out_size)
{
    const float* feat = (const float*)d_in[0];  // [4,256,64,64] f32
    const float* rois = (const float*)d_in[1];  // [N,5] f32
    float* out = (float*)d_out;                 // [N,256,7,7] f32
    const int N = in_sizes[1] / 5;

    dim3 tb(32, 8);
    dim3 tg(NPIX / 32, CCH / 64, 4);
    transpose_kernel<<<tg, tb>>>(feat);

    roialign_maxpool_kernel<<<N * 2, 64>>>(rois, out);
}